// round 1
// baseline (speedup 1.0000x reference)
#include <cuda_runtime.h>
#include <cstdint>

// Problem dims (fixed for this dataset)
#define DD 1024
#define LL 8192
#define BB 4
#define MM (BB*LL)          // 32768 rows
#define LC 128              // scan chunk length
#define NCH (LL/LC)         // 64 chunks per batch

// ---------------- scratch (device globals; no cudaMalloc allowed) ----------------
__device__ float g_rowscale[MM];
__device__ float g_hscale[MM];
__device__ float g_a [(size_t)MM*DD];
__device__ float g_x [(size_t)MM*DD];
__device__ float g_u [(size_t)MM*DD];
__device__ float g_hx[(size_t)MM*DD];     // fallback hx storage if d_out only holds `out`
__device__ float g_sumA[BB*NCH*DD];
__device__ float g_sumH[BB*NCH*DD];
__device__ float g_pre [BB*NCH*DD];

// ---------------- helpers ----------------
__device__ __forceinline__ uint32_t f2tf(float f){
    uint32_t u; asm("cvt.rna.tf32.f32 %0, %1;" : "=r"(u) : "f"(f)); return u;
}
__device__ __forceinline__ float sigm(float v){ return 1.0f/(1.0f + __expf(-v)); }

// ---------------- rmsnorm row scales for `inp` ----------------
__global__ void rowscale_kernel(const float* __restrict__ x, float* __restrict__ out){
    int row  = blockIdx.x*8 + (threadIdx.x >> 5);
    int lane = threadIdx.x & 31;
    const float4* p = (const float4*)(x + (size_t)row*DD);
    float s = 0.f;
    #pragma unroll
    for(int j=0;j<8;j++){
        float4 v = p[lane + j*32];
        s += v.x*v.x + v.y*v.y + v.z*v.z + v.w*v.w;
    }
    #pragma unroll
    for(int o=16;o>0;o>>=1) s += __shfl_xor_sync(0xffffffffu, s, o);
    if(lane==0) out[row] = rsqrtf(s * (1.0f/DD) + 1e-6f);
}

// ---------------- TF32 tensor-core GEMM ----------------
// C[m,n] = sum_k A[m,k]*W[n,k]   (W row-major [N,K] == B col-major KxN for mma row.col)
// MODE 0: dual (Wg,Wc) -> a = 1-sigmoid(Cg), x = sigmoid(Cg)*Cc
// MODE 1: dual (w1,w3) -> u = silu(C1)*C3
// MODE 2: single (w2)  -> out = C + Res
#define BM 128
#define BN 64
#define BK 32
#define AST 36   // padded smem stride (bank-conflict free: banks = 4g+t)

#define MMA_TF32(c, A0,A1,A2,A3, B0,B1) \
  asm volatile("mma.sync.aligned.m16n8k8.row.col.f32.tf32.tf32.f32 " \
    "{%0,%1,%2,%3}, {%4,%5,%6,%7}, {%8,%9}, {%0,%1,%2,%3};\n" \
    : "+f"(c[0]), "+f"(c[1]), "+f"(c[2]), "+f"(c[3]) \
    : "r"(A0), "r"(A1), "r"(A2), "r"(A3), "r"(B0), "r"(B1))

template<int MODE>
__global__ __launch_bounds__(256,2) void gemm_kernel(
    const float* __restrict__ A, const float* __restrict__ rowscale,
    const float* __restrict__ colw,
    const float* __restrict__ W0, const float* __restrict__ W1,
    float* __restrict__ O0, float* __restrict__ O1,
    const float* __restrict__ Res)
{
    constexpr int NW = (MODE==2) ? 1 : 2;
    __shared__ float sA[BM*AST];
    __shared__ float sB[NW][BN*AST];

    const int tid  = threadIdx.x;
    const int m0   = blockIdx.y*BM;
    const int n0   = blockIdx.x*BN;
    const int lane = tid & 31;
    const int wid  = tid >> 5;
    const int wm   = (wid & 3)*32;     // warp M offset (4 warps in M)
    const int wn   = (wid >> 2)*32;    // warp N offset (2 warps in N)
    const int g    = lane >> 2;        // group id 0..7
    const int t    = lane & 3;         // thread-in-group 0..3

    float acc[NW][2][4][4];
    #pragma unroll
    for(int w=0;w<NW;w++)
      #pragma unroll
      for(int mi=0;mi<2;mi++)
        #pragma unroll
        for(int ni=0;ni<4;ni++)
          #pragma unroll
          for(int r=0;r<4;r++) acc[w][mi][ni][r] = 0.f;

    for(int kt=0; kt<DD/BK; ++kt){
        const int k0 = kt*BK;
        __syncthreads();
        // ---- A tile 128x32 (with optional fused row scale / column weight), tf32-rounded
        #pragma unroll
        for(int i=0;i<4;i++){
            int idx = tid + i*256;
            int r = idx >> 3;
            int c = (idx & 7) * 4;
            float4 v = *(const float4*)(A + (size_t)(m0+r)*DD + k0 + c);
            if(rowscale){ float s = rowscale[m0+r]; v.x*=s; v.y*=s; v.z*=s; v.w*=s; }
            if(colw){ float4 w4 = *(const float4*)(colw + k0 + c);
                      v.x*=w4.x; v.y*=w4.y; v.z*=w4.z; v.w*=w4.w; }
            float* d = &sA[r*AST + c];
            d[0]=__uint_as_float(f2tf(v.x)); d[1]=__uint_as_float(f2tf(v.y));
            d[2]=__uint_as_float(f2tf(v.z)); d[3]=__uint_as_float(f2tf(v.w));
        }
        // ---- weight tiles 64x32 each
        #pragma unroll
        for(int w=0;w<NW;w++){
            const float* Wp = (w==0) ? W0 : W1;
            #pragma unroll
            for(int i=0;i<2;i++){
                int idx = tid + i*256;
                int r = idx >> 3;
                int c = (idx & 7) * 4;
                float4 v = *(const float4*)(Wp + (size_t)(n0+r)*DD + k0 + c);
                float* d = &sB[w][r*AST + c];
                d[0]=__uint_as_float(f2tf(v.x)); d[1]=__uint_as_float(f2tf(v.y));
                d[2]=__uint_as_float(f2tf(v.z)); d[3]=__uint_as_float(f2tf(v.w));
            }
        }
        __syncthreads();
        // ---- compute: 4 k8 steps
        #pragma unroll
        for(int kk=0;kk<4;kk++){
            uint32_t afr[2][4];
            #pragma unroll
            for(int mi=0;mi<2;mi++){
                int r0 = wm + mi*16 + g;
                const float* base = &sA[kk*8 + t];
                afr[mi][0] = __float_as_uint(base[(size_t)(r0  )*AST    ]);
                afr[mi][1] = __float_as_uint(base[(size_t)(r0+8)*AST    ]);
                afr[mi][2] = __float_as_uint(base[(size_t)(r0  )*AST + 4]);
                afr[mi][3] = __float_as_uint(base[(size_t)(r0+8)*AST + 4]);
            }
            #pragma unroll
            for(int w=0;w<NW;w++){
                #pragma unroll
                for(int ni=0;ni<4;ni++){
                    int n = wn + ni*8 + g;
                    uint32_t b0 = __float_as_uint(sB[w][n*AST + kk*8 + t    ]);
                    uint32_t b1 = __float_as_uint(sB[w][n*AST + kk*8 + t + 4]);
                    MMA_TF32(acc[w][0][ni], afr[0][0],afr[0][1],afr[0][2],afr[0][3], b0,b1);
                    MMA_TF32(acc[w][1][ni], afr[1][0],afr[1][1],afr[1][2],afr[1][3], b0,b1);
                }
            }
        }
    }

    // ---- epilogue
    #pragma unroll
    for(int mi=0;mi<2;mi++){
        #pragma unroll
        for(int ni=0;ni<4;ni++){
            int mA = m0 + wm + mi*16 + g;
            int nA = n0 + wn + ni*8 + 2*t;
            #pragma unroll
            for(int h=0; h<2; h++){
                int m = mA + h*8;
                size_t off = (size_t)m*DD + nA;
                float v0 = acc[0][mi][ni][h*2+0];
                float v1 = acc[0][mi][ni][h*2+1];
                if constexpr (MODE==0){
                    float u0 = acc[1][mi][ni][h*2+0], u1 = acc[1][mi][ni][h*2+1];
                    float s0 = sigm(v0), s1 = sigm(v1);
                    *(float2*)(O0+off) = make_float2(1.f-s0, 1.f-s1);
                    *(float2*)(O1+off) = make_float2(s0*u0, s1*u1);
                } else if constexpr (MODE==1){
                    float u0 = acc[1][mi][ni][h*2+0], u1 = acc[1][mi][ni][h*2+1];
                    *(float2*)(O0+off) = make_float2(v0*sigm(v0)*u0, v1*sigm(v1)*u1);
                } else {
                    float2 r = *(const float2*)(Res+off);
                    *(float2*)(O0+off) = make_float2(v0 + r.x, v1 + r.y);
                }
            }
        }
    }
}

// ---------------- scan: h_t = a_t * h_{t-1} + x_t along L, per (b,d) ----------------
// pass1: local scan per chunk, store local h + chunk summary (Aprod, Hend)
__global__ __launch_bounds__(1024) void scan1_kernel(
    const float* __restrict__ a, const float* __restrict__ x, float* __restrict__ hloc)
{
    int b = blockIdx.y, ch = blockIdx.x, d = threadIdx.x;
    size_t base = ((size_t)(b*LL + ch*LC))*DD + d;
    float h = 0.f, p = 1.f;
    for(int l=0;l<LC;l++){
        float av = a[base], xv = x[base];
        h = fmaf(av, h, xv);
        p *= av;
        hloc[base] = h;
        base += DD;
    }
    int si = (b*NCH + ch)*DD + d;
    g_sumA[si] = p;
    g_sumH[si] = h;
}

// pass2: serial scan over chunk summaries -> prefix H before each chunk
__global__ __launch_bounds__(1024) void scan2_kernel(){
    int b = blockIdx.x, d = threadIdx.x;
    float H = 0.f;
    for(int ch=0; ch<NCH; ch++){
        int si = (b*NCH + ch)*DD + d;
        g_pre[si] = H;
        H = fmaf(g_sumA[si], H, g_sumH[si]);
    }
}

// pass3: h = hloc + cumprod(a)*Hprev (in place), fused FFN-rmsnorm row scales
__global__ __launch_bounds__(1024) void scan3_kernel(
    const float* __restrict__ a, float* __restrict__ hx, float* __restrict__ hscale)
{
    __shared__ float red[32];
    int b = blockIdx.y, ch = blockIdx.x, d = threadIdx.x;
    int lane = d & 31, wrp = d >> 5;
    float Hp = g_pre[(b*NCH + ch)*DD + d];
    size_t base = ((size_t)(b*LL + ch*LC))*DD + d;
    float p = 1.f;
    for(int l=0;l<LC;l++){
        float av = a[base];
        p *= av;
        float h = fmaf(p, Hp, hx[base]);
        hx[base] = h;
        float s = h*h;
        #pragma unroll
        for(int o=16;o>0;o>>=1) s += __shfl_xor_sync(0xffffffffu, s, o);
        if(lane==0) red[wrp] = s;
        __syncthreads();
        if(d < 32){
            float v = red[d];
            #pragma unroll
            for(int o=16;o>0;o>>=1) v += __shfl_xor_sync(0xffffffffu, v, o);
            if(d==0) hscale[b*LL + ch*LC + l] = rsqrtf(v * (1.0f/DD) + 1e-6f);
        }
        __syncthreads();
        base += DD;
    }
}

// ---------------- launcher ----------------
extern "C" void kernel_launch(void* const* d_in, const int* in_sizes, int n_in,
                              void* d_out, int out_size)
{
    const float* inp = (const float*)d_in[0];
    const float* Wg  = (const float*)d_in[1];
    const float* Wc  = (const float*)d_in[2];
    const float* w1  = (const float*)d_in[3];
    const float* w2  = (const float*)d_in[4];
    const float* w3  = (const float*)d_in[5];
    const float* lnw = (const float*)d_in[6];
    const float* ffw = (const float*)d_in[7];
    float* out = (float*)d_out;

    float *pa, *px, *pu, *phx, *prs, *phs;
    cudaGetSymbolAddress((void**)&pa,  g_a);
    cudaGetSymbolAddress((void**)&px,  g_x);
    cudaGetSymbolAddress((void**)&pu,  g_u);
    cudaGetSymbolAddress((void**)&phx, g_hx);
    cudaGetSymbolAddress((void**)&prs, g_rowscale);
    cudaGetSymbolAddress((void**)&phs, g_hscale);

    // Output layout: (out, hx_next) concatenated. If d_out only fits `out`,
    // keep hx in scratch.
    float* hx = ((long long)out_size >= 2LL*MM*DD) ? (out + (size_t)MM*DD) : phx;

    dim3 ggrid(DD/BN, MM/BM);   // (16, 256)

    // 1) rmsnorm #1 row scales
    rowscale_kernel<<<MM/8, 256>>>(inp, prs);
    // 2) dual GEMM: beta-logits & candidate; epilogue -> a, x
    gemm_kernel<0><<<ggrid, 256>>>(inp, prs, lnw, Wg, Wc, pa, px, nullptr);
    // 3-5) linear recurrence scan (chunked 3-pass); pass3 fuses FFN-rmsnorm scales
    scan1_kernel<<<dim3(NCH, BB), 1024>>>(pa, px, hx);
    scan2_kernel<<<BB, 1024>>>();
    scan3_kernel<<<dim3(NCH, BB), 1024>>>(pa, hx, phs);
    // 6) dual GEMM: w1/w3 with fused SwiGLU -> u
    gemm_kernel<1><<<ggrid, 256>>>(hx, phs, ffw, w1, w3, pu, nullptr, nullptr);
    // 7) GEMM: w2 with fused residual add -> out
    gemm_kernel<2><<<ggrid, 256>>>(pu, nullptr, nullptr, w2, nullptr, out, nullptr, hx);
}

// round 3
// speedup vs baseline: 1.5731x; 1.5731x over previous
#include <cuda_runtime.h>
#include <cstdint>

#define DD 1024
#define LL 8192
#define BB 4
#define MM (BB*LL)          // 32768 rows
#define LC 128
#define NCH (LL/LC)

// ---------------- scratch (device globals; no cudaMalloc allowed) ----------------
__device__ float g_a [(size_t)MM*DD];
__device__ float g_x [(size_t)MM*DD];   // x, later hn
__device__ float g_u [(size_t)MM*DD];   // An, later u
__device__ float g_hx[(size_t)MM*DD];
__device__ float g_wr[5*(size_t)DD*DD]; // rounded weights: Wg,Wc,w1,w3,w2
__device__ float g_sumA[BB*NCH*DD];
__device__ float g_sumH[BB*NCH*DD];
__device__ float g_pre [BB*NCH*DD];

// ---------------- helpers ----------------
__device__ __forceinline__ uint32_t smem_u32(const void* p){
    uint32_t a; asm("{ .reg .u64 t; cvta.to.shared.u64 t, %1; cvt.u32.u64 %0, t; }" : "=r"(a) : "l"(p));
    return a;
}
__device__ __forceinline__ uint32_t f2tf(float f){
    uint32_t u; asm("cvt.rna.tf32.f32 %0, %1;" : "=r"(u) : "f"(f)); return u;
}
__device__ __forceinline__ float rtf(float f){ return __uint_as_float(f2tf(f)); }
__device__ __forceinline__ float sigm(float v){ return 1.0f/(1.0f + __expf(-v)); }

__device__ __forceinline__ void cp16(uint32_t dst, const void* src){
    asm volatile("cp.async.cg.shared.global [%0], [%1], 16;" :: "r"(dst), "l"(src));
}
__device__ __forceinline__ void ldsm4(uint32_t &r0, uint32_t &r1, uint32_t &r2, uint32_t &r3, uint32_t addr){
    asm volatile("ldmatrix.sync.aligned.m8n8.x4.shared.b16 {%0,%1,%2,%3}, [%4];"
        : "=r"(r0), "=r"(r1), "=r"(r2), "=r"(r3) : "r"(addr));
}

#define MMA_TF32(c, A0,A1,A2,A3, B0,B1) \
  asm volatile("mma.sync.aligned.m16n8k8.row.col.f32.tf32.tf32.f32 " \
    "{%0,%1,%2,%3}, {%4,%5,%6,%7}, {%8,%9}, {%0,%1,%2,%3};\n" \
    : "+f"(c[0]), "+f"(c[1]), "+f"(c[2]), "+f"(c[3]) \
    : "r"(A0), "r"(A1), "r"(A2), "r"(A3), "r"(B0), "r"(B1))

// ---------------- pipelined TF32 tensor-core GEMM ----------------
// C[m,n] = sum_k A[m,k]*W[n,k], W row-major [N,K], all operands pre-rounded to tf32.
// Block tile: 128(M) x 64(N per weight), BK=32, 3-stage cp.async pipeline,
// SW128-swizzled smem + ldmatrix.x4 fragment loads.
// MODE 0: dual (Wg,Wc) -> a = 1-sigmoid(Cg), x = sigmoid(Cg)*Cc
// MODE 1: dual (w1,w3) -> u = round_tf32(silu(C1)*C3)
// MODE 2: single (w2)  -> out = C + Res
template<int MODE>
__global__ __launch_bounds__(256, 2) void gemm_tc(
    const float* __restrict__ A, const float* __restrict__ W0, const float* __restrict__ W1,
    float* __restrict__ O0, float* __restrict__ O1, const float* __restrict__ Res)
{
    constexpr int NW = (MODE==2) ? 1 : 2;
    constexpr int STAGE = 16384 + NW*8192;   // A 128x32f (16KB) + NW * B 64x32f (8KB)

    extern __shared__ __align__(1024) char smem[];
    uint32_t sb = smem_u32(smem);
    const int tid  = threadIdx.x, wid = tid >> 5, lane = tid & 31;
    const int m0 = blockIdx.y*128, n0 = blockIdx.x*64;
    const int wm = (wid & 3)*32;    // 4 warps in M
    const int wn = (wid >> 2)*32;   // 2 warps in N
    const int tl = lane >> 3, tr = lane & 7;

    // ldmatrix row indices (per-thread, tile = tl)
    int arow[2];
    arow[0] = wm + 0*16 + (tl&1)*8 + tr;
    arow[1] = wm + 1*16 + (tl&1)*8 + tr;
    int brow[2];
    brow[0] = wn + 0*16 + (tl>>1)*8 + tr;
    brow[1] = wn + 1*16 + (tl>>1)*8 + tr;
    const int aco = tl >> 1;   // A chunk offset (0 -> k, 1 -> k+4)
    const int bco = tl & 1;    // B chunk offset

    float acc[NW][2][4][4];
    #pragma unroll
    for(int w=0;w<NW;w++)
      #pragma unroll
      for(int mi=0;mi<2;mi++)
        #pragma unroll
        for(int ni=0;ni<4;ni++)
          #pragma unroll
          for(int r=0;r<4;r++) acc[w][mi][ni][r] = 0.f;

    auto load_stage = [&](int kt){
        uint32_t base = sb + (kt%3)*STAGE;
        const float* ap = A + (size_t)m0*DD + kt*32;
        #pragma unroll
        for(int i=0;i<4;i++){            // 1024 chunks of 16B over 256 threads
            int idx = tid + i*256; int r = idx>>3, c = idx&7;
            cp16(base + r*128 + (((c)^(r&7))<<4), ap + (size_t)r*DD + c*4);
        }
        #pragma unroll
        for(int w=0; w<NW; w++){
            const float* bp = (w ? W1 : W0) + (size_t)n0*DD + kt*32;
            uint32_t bb = base + 16384 + w*8192;
            #pragma unroll
            for(int i=0;i<2;i++){        // 512 chunks
                int idx = tid + i*256; int r = idx>>3, c = idx&7;
                cp16(bb + r*128 + (((c)^(r&7))<<4), bp + (size_t)r*DD + c*4);
            }
        }
    };

    load_stage(0); asm volatile("cp.async.commit_group;" ::: "memory");
    load_stage(1); asm volatile("cp.async.commit_group;" ::: "memory");

    for(int kt=0; kt<32; kt++){
        asm volatile("cp.async.wait_group 1;" ::: "memory");
        __syncthreads();
        uint32_t base = sb + (kt%3)*STAGE;
        #pragma unroll
        for(int kk=0;kk<4;kk++){
            uint32_t afr[2][4];
            #pragma unroll
            for(int mi=0;mi<2;mi++){
                uint32_t ad = base + arow[mi]*128 + (((2*kk + aco) ^ (arow[mi]&7))<<4);
                ldsm4(afr[mi][0], afr[mi][1], afr[mi][2], afr[mi][3], ad);
            }
            #pragma unroll
            for(int w=0; w<NW; w++){
                #pragma unroll
                for(int p=0;p<2;p++){
                    uint32_t b0,b1,b2,b3;
                    uint32_t bd = base + 16384 + w*8192 + brow[p]*128
                                + (((2*kk + bco) ^ (brow[p]&7))<<4);
                    ldsm4(b0,b1,b2,b3, bd);
                    MMA_TF32(acc[w][0][2*p  ], afr[0][0],afr[0][1],afr[0][2],afr[0][3], b0,b1);
                    MMA_TF32(acc[w][1][2*p  ], afr[1][0],afr[1][1],afr[1][2],afr[1][3], b0,b1);
                    MMA_TF32(acc[w][0][2*p+1], afr[0][0],afr[0][1],afr[0][2],afr[0][3], b2,b3);
                    MMA_TF32(acc[w][1][2*p+1], afr[1][0],afr[1][1],afr[1][2],afr[1][3], b2,b3);
                }
            }
        }
        __syncthreads();
        if (kt+2 < 32) load_stage(kt+2);
        asm volatile("cp.async.commit_group;" ::: "memory");
    }

    // ---- epilogue (registers -> gmem, fused activations)
    const int g = lane >> 2, t = lane & 3;
    #pragma unroll
    for(int mi=0;mi<2;mi++){
        #pragma unroll
        for(int ni=0;ni<4;ni++){
            int mA = m0 + wm + mi*16 + g;
            int nA = n0 + wn + ni*8 + 2*t;
            #pragma unroll
            for(int h=0; h<2; h++){
                int m = mA + h*8;
                size_t off = (size_t)m*DD + nA;
                float v0 = acc[0][mi][ni][h*2+0];
                float v1 = acc[0][mi][ni][h*2+1];
                if constexpr (MODE==0){
                    float u0 = acc[1][mi][ni][h*2+0], u1 = acc[1][mi][ni][h*2+1];
                    float s0 = sigm(v0), s1 = sigm(v1);
                    *(float2*)(O0+off) = make_float2(1.f-s0, 1.f-s1);
                    *(float2*)(O1+off) = make_float2(s0*u0, s1*u1);
                } else if constexpr (MODE==1){
                    float u0 = acc[1][mi][ni][h*2+0], u1 = acc[1][mi][ni][h*2+1];
                    *(float2*)(O0+off) = make_float2(rtf(v0*sigm(v0)*u0), rtf(v1*sigm(v1)*u1));
                } else {
                    float2 r = *(const float2*)(Res+off);
                    *(float2*)(O0+off) = make_float2(v0 + r.x, v1 + r.y);
                }
            }
        }
    }
}

// ---------------- prep kernels ----------------
__global__ void round_kernel(const float4* __restrict__ src, float4* __restrict__ dst, int n4){
    int i = blockIdx.x*256 + threadIdx.x;
    if (i < n4){
        float4 v = src[i];
        dst[i] = make_float4(rtf(v.x), rtf(v.y), rtf(v.z), rtf(v.w));
    }
}

// rmsnorm(inp)*ln_w, rounded to tf32 -> An
__global__ void prep_inp_kernel(const float* __restrict__ x, const float* __restrict__ lnw,
                                float* __restrict__ An){
    int row  = blockIdx.x*8 + (threadIdx.x >> 5);
    int lane = threadIdx.x & 31;
    const float4* p = (const float4*)(x + (size_t)row*DD);
    float4* q = (float4*)(An + (size_t)row*DD);
    const float4* wp = (const float4*)lnw;
    float4 v[8];
    float s = 0.f;
    #pragma unroll
    for(int j=0;j<8;j++){
        v[j] = p[lane + j*32];
        s += v[j].x*v[j].x + v[j].y*v[j].y + v[j].z*v[j].z + v[j].w*v[j].w;
    }
    #pragma unroll
    for(int o=16;o>0;o>>=1) s += __shfl_xor_sync(0xffffffffu, s, o);
    float rs = rsqrtf(s * (1.0f/DD) + 1e-6f);
    #pragma unroll
    for(int j=0;j<8;j++){
        float4 w4 = wp[lane + j*32];
        q[lane + j*32] = make_float4(rtf(v[j].x*rs*w4.x), rtf(v[j].y*rs*w4.y),
                                     rtf(v[j].z*rs*w4.z), rtf(v[j].w*rs*w4.w));
    }
}

// ---------------- scan ----------------
__global__ __launch_bounds__(1024) void scan1_kernel(
    const float* __restrict__ a, const float* __restrict__ x, float* __restrict__ hloc)
{
    int b = blockIdx.y, ch = blockIdx.x, d = threadIdx.x;
    size_t base = ((size_t)(b*LL + ch*LC))*DD + d;
    float h = 0.f, p = 1.f;
    #pragma unroll 4
    for(int l=0;l<LC;l++){
        float av = a[base], xv = x[base];
        h = fmaf(av, h, xv);
        p *= av;
        hloc[base] = h;
        base += DD;
    }
    int si = (b*NCH + ch)*DD + d;
    g_sumA[si] = p;
    g_sumH[si] = h;
}

__global__ __launch_bounds__(1024) void scan2_kernel(){
    int b = blockIdx.x, d = threadIdx.x;
    float H = 0.f;
    #pragma unroll 8
    for(int ch=0; ch<NCH; ch++){
        int si = (b*NCH + ch)*DD + d;
        g_pre[si] = H;
        H = fmaf(g_sumA[si], H, g_sumH[si]);
    }
}

// pass3: finalize hx; fused FFN rmsnorm -> hn = round_tf32(h * rs * ffw)
__global__ __launch_bounds__(1024) void scan3_kernel(
    const float* __restrict__ a, float* __restrict__ hx,
    const float* __restrict__ ffw, float* __restrict__ hn)
{
    __shared__ float red[32];
    __shared__ float s_scale;
    int b = blockIdx.y, ch = blockIdx.x, d = threadIdx.x;
    int lane = d & 31, wrp = d >> 5;
    float Hp = g_pre[(b*NCH + ch)*DD + d];
    float fw = ffw[d];
    size_t base = ((size_t)(b*LL + ch*LC))*DD + d;
    float p = 1.f;
    for(int l=0;l<LC;l++){
        float av = a[base];
        p *= av;
        float h = fmaf(p, Hp, hx[base]);
        hx[base] = h;
        float s = h*h;
        #pragma unroll
        for(int o=16;o>0;o>>=1) s += __shfl_xor_sync(0xffffffffu, s, o);
        if(lane==0) red[wrp] = s;
        __syncthreads();
        if(d < 32){
            float v = red[d];
            #pragma unroll
            for(int o=16;o>0;o>>=1) v += __shfl_xor_sync(0xffffffffu, v, o);
            if(d==0) s_scale = rsqrtf(v * (1.0f/DD) + 1e-6f);
        }
        __syncthreads();
        hn[base] = __uint_as_float(f2tf(h * s_scale * fw));
        base += DD;
    }
}

// ---------------- launcher ----------------
extern "C" void kernel_launch(void* const* d_in, const int* in_sizes, int n_in,
                              void* d_out, int out_size)
{
    const float* inp = (const float*)d_in[0];
    const float* Wg  = (const float*)d_in[1];
    const float* Wc  = (const float*)d_in[2];
    const float* w1  = (const float*)d_in[3];
    const float* w2  = (const float*)d_in[4];
    const float* w3  = (const float*)d_in[5];
    const float* lnw = (const float*)d_in[6];
    const float* ffw = (const float*)d_in[7];
    float* out = (float*)d_out;

    float *pa, *px, *pu, *phx, *pwr;
    cudaGetSymbolAddress((void**)&pa,  g_a);
    cudaGetSymbolAddress((void**)&px,  g_x);
    cudaGetSymbolAddress((void**)&pu,  g_u);
    cudaGetSymbolAddress((void**)&phx, g_hx);
    cudaGetSymbolAddress((void**)&pwr, g_wr);

    float* hx = ((long long)out_size >= 2LL*MM*DD) ? (out + (size_t)MM*DD) : phx;

    const int SM2 = 3*(16384 + 2*8192);  // 98304 dual
    const int SM1 = 3*(16384 + 1*8192);  // 73728 single
    cudaFuncSetAttribute(gemm_tc<0>, cudaFuncAttributeMaxDynamicSharedMemorySize, SM2);
    cudaFuncSetAttribute(gemm_tc<1>, cudaFuncAttributeMaxDynamicSharedMemorySize, SM2);
    cudaFuncSetAttribute(gemm_tc<2>, cudaFuncAttributeMaxDynamicSharedMemorySize, SM1);

    const size_t WN = (size_t)DD*DD;
    // round weights to tf32 (RN) once per launch
    round_kernel<<<1024, 256>>>((const float4*)Wg, (float4*)(pwr + 0*WN), WN/4);
    round_kernel<<<1024, 256>>>((const float4*)Wc, (float4*)(pwr + 1*WN), WN/4);
    round_kernel<<<1024, 256>>>((const float4*)w1, (float4*)(pwr + 2*WN), WN/4);
    round_kernel<<<1024, 256>>>((const float4*)w3, (float4*)(pwr + 3*WN), WN/4);
    round_kernel<<<1024, 256>>>((const float4*)w2, (float4*)(pwr + 4*WN), WN/4);
    // An = round(rmsnorm(inp)*lnw) -> g_u
    prep_inp_kernel<<<MM/8, 256>>>(inp, lnw, pu);

    dim3 ggrid(16, 256);   // (DD/64, MM/128)
    // dual GEMM (Wg,Wc): a -> g_a, x -> g_x
    gemm_tc<0><<<ggrid, 256, SM2>>>(pu, pwr + 0*WN, pwr + 1*WN, pa, px, nullptr);
    // linear recurrence
    scan1_kernel<<<dim3(NCH, BB), 1024>>>(pa, px, hx);
    scan2_kernel<<<BB, 1024>>>();
    scan3_kernel<<<dim3(NCH, BB), 1024>>>(pa, hx, ffw, px);   // hn -> g_x
    // dual GEMM (w1,w3) with SwiGLU: u -> g_u
    gemm_tc<1><<<ggrid, 256, SM2>>>(px, pwr + 2*WN, pwr + 3*WN, pu, nullptr, nullptr);
    // GEMM (w2) + residual: out
    gemm_tc<2><<<ggrid, 256, SM1>>>(pu, pwr + 4*WN, nullptr, out, nullptr, hx);
}